// round 2
// baseline (speedup 1.0000x reference)
#include <cuda_runtime.h>
#include <cuda_bf16.h>
#include <cstddef>

// Problem constants
#define S 2048
#define E 1024
#define H 16
#define HD 64
#define P 64
#define SCALE 0.125f   // 1/sqrt(64)

// Scratch (allocation-free rule: __device__ globals)
__device__ float g_q[S * E];
__device__ float g_k[S * E];
__device__ float g_v[S * E];
__device__ float g_rel[S * S];
__device__ float g_attn[S * E];

// Packed f32x2 FMA: d = a*b + d (elementwise on packed pairs)
__device__ __forceinline__ void ffma2(unsigned long long& d,
                                      unsigned long long a,
                                      unsigned long long b) {
    asm("fma.rn.f32x2 %0, %1, %2, %0;" : "+l"(d) : "l"(a), "l"(b));
}

__device__ __forceinline__ void unpack2(unsigned long long v, float& lo, float& hi) {
    asm("mov.b64 {%0, %1}, %2;" : "=f"(lo), "=f"(hi) : "l"(v));
}

// ---------------------------------------------------------------------------
// GEMM: C[M,N] = A[M,K] * B[N,K]^T (+ bias[N])
// BM=BN=128, BK=8, 256 threads, 8x8 per thread, FFMA2 double-pumped.
// A tile stored DUPLICATED in smem so LDS.128 yields {a,a} packed pairs.
// ---------------------------------------------------------------------------
__global__ __launch_bounds__(256) void gemm128_abt(
    const float* __restrict__ A, const float* __restrict__ B,
    const float* __restrict__ bias, float* __restrict__ C,
    int K, int lda, int ldb, int ldc)
{
    __shared__ float As2[8][264];   // duplicated: As2[c][2r]=As2[c][2r+1]
    __shared__ float Bs[8][132];
    const int tid = threadIdx.x;
    const int tx = tid & 15, ty = tid >> 4;
    const int row0 = blockIdx.y * 128;
    const int col0 = blockIdx.x * 128;

    unsigned long long acc[8][4];
#pragma unroll
    for (int i = 0; i < 8; i++)
#pragma unroll
        for (int j = 0; j < 4; j++) acc[i][j] = 0ULL;

    for (int k0 = 0; k0 < K; k0 += 8) {
#pragma unroll
        for (int i = 0; i < 4; i++) {
            int idx = tid + i * 256;
            int r = idx >> 3, c = idx & 7;
            float av = A[(size_t)(row0 + r) * lda + k0 + c];
            *(float2*)&As2[c][2 * r] = make_float2(av, av);
            Bs[c][r] = B[(size_t)(col0 + r) * ldb + k0 + c];
        }
        __syncthreads();
#pragma unroll
        for (int kk = 0; kk < 8; kk++) {
            unsigned long long a[8], b[4];
            ulonglong2 t;
            t = *(const ulonglong2*)&As2[kk][ty * 8];        a[0] = t.x; a[1] = t.y;
            t = *(const ulonglong2*)&As2[kk][ty * 8 + 4];    a[2] = t.x; a[3] = t.y;
            t = *(const ulonglong2*)&As2[kk][128 + ty * 8];  a[4] = t.x; a[5] = t.y;
            t = *(const ulonglong2*)&As2[kk][132 + ty * 8];  a[6] = t.x; a[7] = t.y;
            t = *(const ulonglong2*)&Bs[kk][tx * 4];         b[0] = t.x; b[1] = t.y;
            t = *(const ulonglong2*)&Bs[kk][64 + tx * 4];    b[2] = t.x; b[3] = t.y;
#pragma unroll
            for (int i = 0; i < 8; i++)
#pragma unroll
                for (int j = 0; j < 4; j++) ffma2(acc[i][j], a[i], b[j]);
        }
        __syncthreads();
    }

#pragma unroll
    for (int i = 0; i < 8; i++) {
        int r = row0 + ((i < 4) ? (ty * 4 + i) : (64 + ty * 4 + i - 4));
#pragma unroll
        for (int j = 0; j < 4; j++) {
            int c = col0 + ((j < 2) ? (tx * 4 + 2 * j) : (64 + tx * 4 + 2 * (j - 2)));
            float lo, hi;
            unpack2(acc[i][j], lo, hi);
            if (bias) { lo += bias[c]; hi += bias[c + 1]; }
            C[(size_t)r * ldc + c]     = lo;
            C[(size_t)r * ldc + c + 1] = hi;
        }
    }
}

// ---------------------------------------------------------------------------
// Scores: w[h,s,t] = (q_h[s,:]·k_h[t,:] + rel[s,t]) * SCALE   (raw, pre-softmax)
// ---------------------------------------------------------------------------
__global__ __launch_bounds__(256) void score128(
    const float* __restrict__ rel, float* __restrict__ w)
{
    const int h = blockIdx.z;
    const float* A = g_q + h * HD;   // lda = E
    const float* B = g_k + h * HD;   // ldb = E
    float* C = w + (size_t)h * S * S;

    __shared__ float As2[8][264];
    __shared__ float Bs[8][132];
    const int tid = threadIdx.x;
    const int tx = tid & 15, ty = tid >> 4;
    const int row0 = blockIdx.y * 128;
    const int col0 = blockIdx.x * 128;

    unsigned long long acc[8][4];
#pragma unroll
    for (int i = 0; i < 8; i++)
#pragma unroll
        for (int j = 0; j < 4; j++) acc[i][j] = 0ULL;

    for (int k0 = 0; k0 < HD; k0 += 8) {
#pragma unroll
        for (int i = 0; i < 4; i++) {
            int idx = tid + i * 256;
            int r = idx >> 3, c = idx & 7;
            float av = A[(size_t)(row0 + r) * E + k0 + c];
            *(float2*)&As2[c][2 * r] = make_float2(av, av);
            Bs[c][r] = B[(size_t)(col0 + r) * E + k0 + c];
        }
        __syncthreads();
#pragma unroll
        for (int kk = 0; kk < 8; kk++) {
            unsigned long long a[8], b[4];
            ulonglong2 t;
            t = *(const ulonglong2*)&As2[kk][ty * 8];        a[0] = t.x; a[1] = t.y;
            t = *(const ulonglong2*)&As2[kk][ty * 8 + 4];    a[2] = t.x; a[3] = t.y;
            t = *(const ulonglong2*)&As2[kk][128 + ty * 8];  a[4] = t.x; a[5] = t.y;
            t = *(const ulonglong2*)&As2[kk][132 + ty * 8];  a[6] = t.x; a[7] = t.y;
            t = *(const ulonglong2*)&Bs[kk][tx * 4];         b[0] = t.x; b[1] = t.y;
            t = *(const ulonglong2*)&Bs[kk][64 + tx * 4];    b[2] = t.x; b[3] = t.y;
#pragma unroll
            for (int i = 0; i < 8; i++)
#pragma unroll
                for (int j = 0; j < 4; j++) ffma2(acc[i][j], a[i], b[j]);
        }
        __syncthreads();
    }

#pragma unroll
    for (int i = 0; i < 8; i++) {
        int r = row0 + ((i < 4) ? (ty * 4 + i) : (64 + ty * 4 + i - 4));
#pragma unroll
        for (int j = 0; j < 4; j++) {
            int c = col0 + ((j < 2) ? (tx * 4 + 2 * j) : (64 + tx * 4 + 2 * (j - 2)));
            float lo, hi;
            unpack2(acc[i][j], lo, hi);
            C[(size_t)r * S + c]     = (lo + rel[(size_t)r * S + c]) * SCALE;
            C[(size_t)r * S + c + 1] = (hi + rel[(size_t)r * S + c + 1]) * SCALE;
        }
    }
}

// ---------------------------------------------------------------------------
// Row softmax in-place over w: one block per (h,s) row of 2048
// ---------------------------------------------------------------------------
__global__ __launch_bounds__(256) void softmax_rows(float* __restrict__ w)
{
    float* p = w + (size_t)blockIdx.x * S;
    const int tid = threadIdx.x;
    __shared__ float red[256];

    float vals[8];
    float mx = -1e30f;
#pragma unroll
    for (int i = 0; i < 8; i++) {
        vals[i] = p[tid + i * 256];
        mx = fmaxf(mx, vals[i]);
    }
    red[tid] = mx;
    __syncthreads();
    for (int s2 = 128; s2 > 0; s2 >>= 1) {
        if (tid < s2) red[tid] = fmaxf(red[tid], red[tid + s2]);
        __syncthreads();
    }
    mx = red[0];
    __syncthreads();

    float sum = 0.f;
#pragma unroll
    for (int i = 0; i < 8; i++) {
        vals[i] = __expf(vals[i] - mx);
        sum += vals[i];
    }
    red[tid] = sum;
    __syncthreads();
    for (int s2 = 128; s2 > 0; s2 >>= 1) {
        if (tid < s2) red[tid] += red[tid + s2];
        __syncthreads();
    }
    float inv = 1.f / red[0];
#pragma unroll
    for (int i = 0; i < 8; i++) p[tid + i * 256] = vals[i] * inv;
}

// ---------------------------------------------------------------------------
// attn[s, h*64+d] = sum_t w[h,s,t] * v[t, h*64+d]
// BM=128, BN=64, BK=16.  FFMA2 double-pumped. grid (1,16,H)
// ---------------------------------------------------------------------------
__global__ __launch_bounds__(256) void attn_gemm(const float* __restrict__ w)
{
    const int h = blockIdx.z;
    const float* A = w + (size_t)h * S * S;   // lda = S
    const float* B = g_v + h * HD;            // B[t][d] = v[t*E + h*HD + d]
    float* C = g_attn + h * HD;               // ldc = E

    __shared__ float As2[16][264];  // duplicated transposed [k][2m]
    __shared__ float Bs[16][64];    // [k][n]
    const int tid = threadIdx.x;
    const int tx = tid & 15, ty = tid >> 4;
    const int row0 = blockIdx.y * 128;

    unsigned long long acc[8][2];
#pragma unroll
    for (int i = 0; i < 8; i++)
#pragma unroll
        for (int j = 0; j < 2; j++) acc[i][j] = 0ULL;

    for (int k0 = 0; k0 < S; k0 += 16) {
#pragma unroll
        for (int i = 0; i < 8; i++) {
            int idx = tid + i * 256;
            int r = idx >> 4, c = idx & 15;
            float av = A[(size_t)(row0 + r) * S + k0 + c];
            *(float2*)&As2[c][2 * r] = make_float2(av, av);
        }
#pragma unroll
        for (int i = 0; i < 4; i++) {
            int idx = tid + i * 256;
            int r = idx >> 6, c = idx & 63;
            Bs[r][c] = B[(size_t)(k0 + r) * E + c];
        }
        __syncthreads();
#pragma unroll
        for (int kk = 0; kk < 16; kk++) {
            unsigned long long a[8], b[2];
            ulonglong2 t;
            t = *(const ulonglong2*)&As2[kk][ty * 8];        a[0] = t.x; a[1] = t.y;
            t = *(const ulonglong2*)&As2[kk][ty * 8 + 4];    a[2] = t.x; a[3] = t.y;
            t = *(const ulonglong2*)&As2[kk][128 + ty * 8];  a[4] = t.x; a[5] = t.y;
            t = *(const ulonglong2*)&As2[kk][132 + ty * 8];  a[6] = t.x; a[7] = t.y;
            t = *(const ulonglong2*)&Bs[kk][tx * 4];         b[0] = t.x; b[1] = t.y;
#pragma unroll
            for (int i = 0; i < 8; i++)
#pragma unroll
                for (int j = 0; j < 2; j++) ffma2(acc[i][j], a[i], b[j]);
        }
        __syncthreads();
    }

#pragma unroll
    for (int i = 0; i < 8; i++) {
        int r = row0 + ((i < 4) ? (ty * 4 + i) : (64 + ty * 4 + i - 4));
#pragma unroll
        for (int j = 0; j < 2; j++) {
            int c = tx * 4 + 2 * j;
            float lo, hi;
            unpack2(acc[i][j], lo, hi);
            C[(size_t)r * E + c]     = lo;
            C[(size_t)r * E + c + 1] = hi;
        }
    }
}

// ---------------------------------------------------------------------------
// Launch
// ---------------------------------------------------------------------------
extern "C" void kernel_launch(void* const* d_in, const int* in_sizes, int n_in,
                              void* d_out, int out_size)
{
    (void)in_sizes; (void)n_in; (void)out_size;
    const float* query = (const float*)d_in[0];
    const float* key   = (const float*)d_in[1];
    const float* value = (const float*)d_in[2];
    const float* sim   = (const float*)d_in[3];
    const float* Wq    = (const float*)d_in[4];
    const float* bq    = (const float*)d_in[5];
    const float* Wk    = (const float*)d_in[6];
    const float* bk    = (const float*)d_in[7];
    const float* Wv    = (const float*)d_in[8];
    const float* bv    = (const float*)d_in[9];
    const float* Wo    = (const float*)d_in[10];
    const float* bo    = (const float*)d_in[11];

    float* out = (float*)d_out;                 // [S,E]
    float* w   = out + (size_t)S * E;           // [H,S,S]

    float *gq, *gk, *gv, *grel, *gattn;
    cudaGetSymbolAddress((void**)&gq,    g_q);
    cudaGetSymbolAddress((void**)&gk,    g_k);
    cudaGetSymbolAddress((void**)&gv,    g_v);
    cudaGetSymbolAddress((void**)&grel,  g_rel);
    cudaGetSymbolAddress((void**)&gattn, g_attn);

    dim3 blk(256);

    // Projections: q/k/v = X @ W^T + b
    gemm128_abt<<<dim3(E / 128, S / 128), blk>>>(query, Wq, bq, gq, E, E, E, E);
    gemm128_abt<<<dim3(E / 128, S / 128), blk>>>(key,   Wk, bk, gk, E, E, E, E);
    gemm128_abt<<<dim3(E / 128, S / 128), blk>>>(value, Wv, bv, gv, E, E, E, E);

    // rel = sim @ sim^T
    gemm128_abt<<<dim3(S / 128, S / 128), blk>>>(sim, sim, nullptr, grel, P, P, P, S);

    // scores (raw) -> w
    score128<<<dim3(S / 128, S / 128, H), blk>>>(grel, w);

    // softmax in place over last dim
    softmax_rows<<<H * S, blk>>>(w);

    // attn = w @ v_h  (per head) -> g_attn [S,E]
    attn_gemm<<<dim3(1, S / 128, H), blk>>>(w);

    // out = attn @ Wo^T + bo
    gemm128_abt<<<dim3(E / 128, S / 128), blk>>>(gattn, Wo, bo, out, E, E, E, E);
}

// round 4
// speedup vs baseline: 1.6826x; 1.6826x over previous
#include <cuda_runtime.h>
#include <cuda_bf16.h>
#include <cstdint>
#include <cstddef>

#define S 2048
#define E 1024
#define H 16
#define HD 64
#define SCALE 0.125f

// Scratch
__device__ float g_q[S * E];
__device__ float g_k[S * E];
__device__ float g_v[S * E];
__device__ float g_rel[S * S];
__device__ float g_attn[S * E];

// ---------------------------------------------------------------------------
// Helpers
// ---------------------------------------------------------------------------
__device__ __forceinline__ uint32_t smem_u32(const void* p) {
    uint32_t a;
    asm("{ .reg .u64 t; cvta.to.shared.u64 t, %1; cvt.u32.u64 %0, t; }"
        : "=r"(a) : "l"(p));
    return a;
}

__device__ __forceinline__ uint32_t sw128(uint32_t off) {
    return off ^ ((off >> 3) & 0x70);
}

__device__ __forceinline__ void ldsm4(uint32_t* r, uint32_t addr) {
    asm volatile("ldmatrix.sync.aligned.m8n8.x4.shared.b16 {%0,%1,%2,%3}, [%4];"
                 : "=r"(r[0]), "=r"(r[1]), "=r"(r[2]), "=r"(r[3]) : "r"(addr));
}

__device__ __forceinline__ void mma16816(float* c, const uint32_t* a, const uint32_t* b) {
    asm volatile(
        "mma.sync.aligned.m16n8k16.row.col.f32.bf16.bf16.f32 "
        "{%0,%1,%2,%3}, {%4,%5,%6,%7}, {%8,%9}, {%0,%1,%2,%3};"
        : "+f"(c[0]), "+f"(c[1]), "+f"(c[2]), "+f"(c[3])
        : "r"(a[0]), "r"(a[1]), "r"(a[2]), "r"(a[3]), "r"(b[0]), "r"(b[1]));
}

// Split fp32 pair -> bf16 hi/lo pairs into SW128 row: [hi 32 bf16 | lo 32 bf16]
__device__ __forceinline__ void split_store_pair(char* base, int row, int col2,
                                                 float x0, float x1) {
    __nv_bfloat16 h0 = __float2bfloat16(x0);
    __nv_bfloat16 h1 = __float2bfloat16(x1);
    __nv_bfloat16 l0 = __float2bfloat16(x0 - __bfloat162float(h0));
    __nv_bfloat16 l1 = __float2bfloat16(x1 - __bfloat162float(h1));
    __nv_bfloat162 hp; hp.x = h0; hp.y = h1;
    __nv_bfloat162 lp; lp.x = l0; lp.y = l1;
    *(__nv_bfloat162*)(base + sw128(row * 128 + col2 * 2)) = hp;
    *(__nv_bfloat162*)(base + sw128(row * 128 + 64 + col2 * 2)) = lp;
}

// Slice offsets (bf16 cols): (A,B) in {(hi,hi),(hi,lo),(lo,hi)}
__constant__ int c_aofs[3] = {0, 0, 32};
__constant__ int c_bofs[3] = {0, 32, 0};

// ---------------------------------------------------------------------------
// tc_gemm: C[M,N] = A[M,K]*B[N,K]^T (bf16x3). Tile 128x128, BK=32, 8 warps.
// mode 0: +bias (optional)   mode 1: C = (acc + rel) * SCALE
// ---------------------------------------------------------------------------
__global__ __launch_bounds__(256) void tc_gemm(
    const float* __restrict__ Ag, const float* __restrict__ Bg,
    float* __restrict__ Cg, int K, int lda, int ldb, int ldc,
    long strideAz, long strideBz, long strideCz,
    const float* __restrict__ bias, const float* __restrict__ rel, int mode)
{
    __shared__ __align__(128) char smA[128 * 128];
    __shared__ __align__(128) char smB[128 * 128];

    const int tid = threadIdx.x;
    const int warp = tid >> 5, lane = tid & 31;
    const int z = blockIdx.z;
    const float* A = Ag + (long)z * strideAz;
    const float* B = Bg + (long)z * strideBz;
    float* C = Cg + (long)z * strideCz;
    const int row0 = blockIdx.y * 128;
    const int col0 = blockIdx.x * 128;
    const int wm0 = (warp >> 1) * 32;
    const int wn0 = (warp & 1) * 64;

    uint32_t sA = smem_u32(smA);
    uint32_t sB = smem_u32(smB);

    float c[2][8][4];
#pragma unroll
    for (int i = 0; i < 2; i++)
#pragma unroll
        for (int j = 0; j < 8; j++)
#pragma unroll
            for (int t = 0; t < 4; t++) c[i][j][t] = 0.f;

    const int lr = tid >> 4;       // 0..15
    const int lp = tid & 15;       // 0..15

    for (int k0 = 0; k0 < K; k0 += 32) {
#pragma unroll
        for (int s = 0; s < 8; s++) {
            int r = s * 16 + lr;
            float2 va = *(const float2*)&A[(size_t)(row0 + r) * lda + k0 + 2 * lp];
            split_store_pair(smA, r, 2 * lp, va.x, va.y);
            float2 vb = *(const float2*)&B[(size_t)(col0 + r) * ldb + k0 + 2 * lp];
            split_store_pair(smB, r, 2 * lp, vb.x, vb.y);
        }
        __syncthreads();

        const int arow = wm0 + (lane & 15);
        const int acolq = (lane >> 4) * 8;               // 0 or 8
        const int bn = wn0 + (lane & 7) + ((lane >> 4) << 3);
        const int bkq = ((lane >> 3) & 1) * 8;           // 0 or 8

#pragma unroll
        for (int s3 = 0; s3 < 3; s3++) {
            const int aoff = c_aofs[s3], boff = c_bofs[s3];
#pragma unroll
            for (int ks = 0; ks < 2; ks++) {
                int acol = aoff + ks * 16 + acolq;
                uint32_t a0[4], a1[4];
                ldsm4(a0, sA + sw128((uint32_t)(arow * 128 + acol * 2)));
                ldsm4(a1, sA + sw128((uint32_t)((arow + 16) * 128 + acol * 2)));
                int bcol = boff + ks * 16 + bkq;
                uint32_t bq[4][4];
#pragma unroll
                for (int j2 = 0; j2 < 4; j2++)
                    ldsm4(bq[j2], sB + sw128((uint32_t)((bn + j2 * 16) * 128 + bcol * 2)));
#pragma unroll
                for (int i = 0; i < 2; i++) {
                    const uint32_t* ai = (i == 0) ? a0 : a1;
#pragma unroll
                    for (int j = 0; j < 8; j++)
                        mma16816(c[i][j], ai, &bq[j >> 1][(j & 1) * 2]);
                }
            }
        }
        __syncthreads();
    }

    // Epilogue
    const int g = lane >> 2, t4 = lane & 3;
#pragma unroll
    for (int i = 0; i < 2; i++) {
#pragma unroll
        for (int j = 0; j < 8; j++) {
            int gr0 = row0 + wm0 + i * 16 + g;
            int gc = col0 + wn0 + j * 8 + t4 * 2;
            float v0 = c[i][j][0], v1 = c[i][j][1];
            float v2 = c[i][j][2], v3 = c[i][j][3];
            if (mode == 1) {
                float2 r0 = *(const float2*)&rel[(size_t)gr0 * S + gc];
                float2 r1 = *(const float2*)&rel[(size_t)(gr0 + 8) * S + gc];
                v0 = (v0 + r0.x) * SCALE; v1 = (v1 + r0.y) * SCALE;
                v2 = (v2 + r1.x) * SCALE; v3 = (v3 + r1.y) * SCALE;
            } else if (bias) {
                float2 bv = *(const float2*)&bias[gc];
                v0 += bv.x; v1 += bv.y; v2 += bv.x; v3 += bv.y;
            }
            *(float2*)&C[(size_t)gr0 * ldc + gc] = make_float2(v0, v1);
            *(float2*)&C[(size_t)(gr0 + 8) * ldc + gc] = make_float2(v2, v3);
        }
    }
}

// ---------------------------------------------------------------------------
// tc_pv: attn[s, h*64+d] = sum_t w[h,s,t] * v[t, h*64+d]
// Tile 128x64, BK=32. B = v^T gathered on the fly.
// ---------------------------------------------------------------------------
__global__ __launch_bounds__(256) void tc_pv(const float* __restrict__ w)
{
    __shared__ __align__(128) char smA[128 * 128];
    __shared__ __align__(128) char smB[64 * 128];

    const int tid = threadIdx.x;
    const int warp = tid >> 5, lane = tid & 31;
    const int h = blockIdx.z;
    const int row0 = blockIdx.y * 128;
    const int hbase = h * HD;
    const float* A = w + (size_t)h * S * S;
    const int wm0 = (warp >> 1) * 32;
    const int wn0 = (warp & 1) * 32;

    uint32_t sA = smem_u32(smA);
    uint32_t sB = smem_u32(smB);

    float c[2][4][4];
#pragma unroll
    for (int i = 0; i < 2; i++)
#pragma unroll
        for (int j = 0; j < 4; j++)
#pragma unroll
            for (int t = 0; t < 4; t++) c[i][j][t] = 0.f;

    const int lr = tid >> 4;
    const int lp = tid & 15;

    for (int k0 = 0; k0 < S; k0 += 32) {
#pragma unroll
        for (int s = 0; s < 8; s++) {
            int r = s * 16 + lr;
            float2 va = *(const float2*)&A[(size_t)(row0 + r) * S + k0 + 2 * lp];
            split_store_pair(smA, r, 2 * lp, va.x, va.y);
        }
        // B[d][t] = v[(k0+t)*E + hbase + d], 64 d-rows x 32 t-cols
#pragma unroll
        for (int s = 0; s < 8; s++) {
            int idx = s * 256 + tid;
            int tt = idx >> 6;      // 0..31
            int d = idx & 63;       // 0..63
            float x = g_v[(size_t)(k0 + tt) * E + hbase + d];
            __nv_bfloat16 hi = __float2bfloat16(x);
            __nv_bfloat16 lo = __float2bfloat16(x - __bfloat162float(hi));
            *(__nv_bfloat16*)(smB + sw128((uint32_t)(d * 128 + tt * 2))) = hi;
            *(__nv_bfloat16*)(smB + sw128((uint32_t)(d * 128 + 64 + tt * 2))) = lo;
        }
        __syncthreads();

        const int arow = wm0 + (lane & 15);
        const int acolq = (lane >> 4) * 8;
        const int bn = wn0 + (lane & 7) + ((lane >> 4) << 3);
        const int bkq = ((lane >> 3) & 1) * 8;

#pragma unroll
        for (int s3 = 0; s3 < 3; s3++) {
            const int aoff = c_aofs[s3], boff = c_bofs[s3];
#pragma unroll
            for (int ks = 0; ks < 2; ks++) {
                int acol = aoff + ks * 16 + acolq;
                uint32_t a0[4], a1[4];
                ldsm4(a0, sA + sw128((uint32_t)(arow * 128 + acol * 2)));
                ldsm4(a1, sA + sw128((uint32_t)((arow + 16) * 128 + acol * 2)));
                int bcol = boff + ks * 16 + bkq;
                uint32_t bq[2][4];
#pragma unroll
                for (int j2 = 0; j2 < 2; j2++)
                    ldsm4(bq[j2], sB + sw128((uint32_t)((bn + j2 * 16) * 128 + bcol * 2)));
#pragma unroll
                for (int i = 0; i < 2; i++) {
                    const uint32_t* ai = (i == 0) ? a0 : a1;
#pragma unroll
                    for (int j = 0; j < 4; j++)
                        mma16816(c[i][j], ai, &bq[j >> 1][(j & 1) * 2]);
                }
            }
        }
        __syncthreads();
    }

    const int g = lane >> 2, t4 = lane & 3;
#pragma unroll
    for (int i = 0; i < 2; i++) {
#pragma unroll
        for (int j = 0; j < 4; j++) {
            int gr0 = row0 + wm0 + i * 16 + g;
            int gc = hbase + wn0 + j * 8 + t4 * 2;
            *(float2*)&g_attn[(size_t)gr0 * E + gc] = make_float2(c[i][j][0], c[i][j][1]);
            *(float2*)&g_attn[(size_t)(gr0 + 8) * E + gc] = make_float2(c[i][j][2], c[i][j][3]);
        }
    }
}

// ---------------------------------------------------------------------------
// Row softmax in-place over w
// ---------------------------------------------------------------------------
__global__ __launch_bounds__(256) void softmax_rows(float* __restrict__ w)
{
    float* p = w + (size_t)blockIdx.x * S;
    const int tid = threadIdx.x;
    __shared__ float red[256];

    float vals[8];
    float mx = -1e30f;
#pragma unroll
    for (int i = 0; i < 8; i++) {
        vals[i] = p[tid + i * 256];
        mx = fmaxf(mx, vals[i]);
    }
    red[tid] = mx;
    __syncthreads();
    for (int s2 = 128; s2 > 0; s2 >>= 1) {
        if (tid < s2) red[tid] = fmaxf(red[tid], red[tid + s2]);
        __syncthreads();
    }
    mx = red[0];
    __syncthreads();

    float sum = 0.f;
#pragma unroll
    for (int i = 0; i < 8; i++) {
        vals[i] = __expf(vals[i] - mx);
        sum += vals[i];
    }
    red[tid] = sum;
    __syncthreads();
    for (int s2 = 128; s2 > 0; s2 >>= 1) {
        if (tid < s2) red[tid] += red[tid + s2];
        __syncthreads();
    }
    float inv = 1.f / red[0];
#pragma unroll
    for (int i = 0; i < 8; i++) p[tid + i * 256] = vals[i] * inv;
}

// ---------------------------------------------------------------------------
// Launch
// ---------------------------------------------------------------------------
extern "C" void kernel_launch(void* const* d_in, const int* in_sizes, int n_in,
                              void* d_out, int out_size)
{
    (void)in_sizes; (void)n_in; (void)out_size;
    const float* query = (const float*)d_in[0];
    const float* key   = (const float*)d_in[1];
    const float* value = (const float*)d_in[2];
    const float* sim   = (const float*)d_in[3];
    const float* Wq    = (const float*)d_in[4];
    const float* bq    = (const float*)d_in[5];
    const float* Wk    = (const float*)d_in[6];
    const float* bk    = (const float*)d_in[7];
    const float* Wv    = (const float*)d_in[8];
    const float* bv    = (const float*)d_in[9];
    const float* Wo    = (const float*)d_in[10];
    const float* bo    = (const float*)d_in[11];

    float* out = (float*)d_out;                 // [S,E]
    float* w   = out + (size_t)S * E;           // [H,S,S]

    float *gq, *gk, *gv, *grel, *gattn;
    cudaGetSymbolAddress((void**)&gq,    g_q);
    cudaGetSymbolAddress((void**)&gk,    g_k);
    cudaGetSymbolAddress((void**)&gv,    g_v);
    cudaGetSymbolAddress((void**)&grel,  g_rel);
    cudaGetSymbolAddress((void**)&gattn, g_attn);

    dim3 blk(256);

    // Projections: q/k/v = X @ W^T + b
    tc_gemm<<<dim3(E / 128, S / 128), blk>>>(query, Wq, gq, E, E, E, E, 0, 0, 0, bq, nullptr, 0);
    tc_gemm<<<dim3(E / 128, S / 128), blk>>>(key,   Wk, gk, E, E, E, E, 0, 0, 0, bk, nullptr, 0);
    tc_gemm<<<dim3(E / 128, S / 128), blk>>>(value, Wv, gv, E, E, E, E, 0, 0, 0, bv, nullptr, 0);

    // rel = sim @ sim^T
    tc_gemm<<<dim3(S / 128, S / 128), blk>>>(sim, sim, grel, 64, 64, 64, S, 0, 0, 0, nullptr, nullptr, 0);

    // scores: w[h] = (q_h k_h^T + rel) * SCALE
    tc_gemm<<<dim3(S / 128, S / 128, H), blk>>>(gq, gk, w, HD, E, E, S,
                                                HD, HD, (long)S * S, nullptr, grel, 1);

    // softmax in place over last dim
    softmax_rows<<<H * S, 256>>>(w);

    // attn = w @ v_h (per head)
    tc_pv<<<dim3(1, S / 128, H), blk>>>(w);

    // out = attn @ Wo^T + bo
    tc_gemm<<<dim3(E / 128, S / 128), blk>>>(gattn, Wo, out, E, E, E, E, 0, 0, 0, bo, nullptr, 0);
}

// round 5
// speedup vs baseline: 1.8320x; 1.0888x over previous
#include <cuda_runtime.h>
#include <cuda_bf16.h>
#include <cstdint>
#include <cstddef>

#define S 2048
#define E 1024
#define H 16
#define HD 64
#define SCALE 0.125f

// Scratch
__device__ float g_q[S * E];
__device__ float g_k[S * E];
__device__ float g_v[S * E];
__device__ float g_rel[S * S];
__device__ float g_attn[S * E];

// ---------------------------------------------------------------------------
// Helpers
// ---------------------------------------------------------------------------
__device__ __forceinline__ uint32_t smem_u32(const void* p) {
    uint32_t a;
    asm("{ .reg .u64 t; cvta.to.shared.u64 t, %1; cvt.u32.u64 %0, t; }"
        : "=r"(a) : "l"(p));
    return a;
}

__device__ __forceinline__ uint32_t sw128(uint32_t off) {
    return off ^ ((off >> 3) & 0x70);
}

__device__ __forceinline__ void ldsm4(uint32_t* r, uint32_t addr) {
    asm volatile("ldmatrix.sync.aligned.m8n8.x4.shared.b16 {%0,%1,%2,%3}, [%4];"
                 : "=r"(r[0]), "=r"(r[1]), "=r"(r[2]), "=r"(r[3]) : "r"(addr));
}

__device__ __forceinline__ void mma16816(float* c, const uint32_t* a, const uint32_t* b) {
    asm volatile(
        "mma.sync.aligned.m16n8k16.row.col.f32.bf16.bf16.f32 "
        "{%0,%1,%2,%3}, {%4,%5,%6,%7}, {%8,%9}, {%0,%1,%2,%3};"
        : "+f"(c[0]), "+f"(c[1]), "+f"(c[2]), "+f"(c[3])
        : "r"(a[0]), "r"(a[1]), "r"(a[2]), "r"(a[3]), "r"(b[0]), "r"(b[1]));
}

// pack two floats (lo goes to low 16 bits) as bf16x2
__device__ __forceinline__ uint32_t bf2(float lo, float hi) {
    uint32_t r;
    asm("cvt.rn.bf16x2.f32 %0, %1, %2;" : "=r"(r) : "f"(hi), "f"(lo));
    return r;
}

__device__ __forceinline__ void split2(float x, float y, uint32_t& hi, uint32_t& lo) {
    __nv_bfloat16 bx = __float2bfloat16(x), by = __float2bfloat16(y);
    __nv_bfloat162 hp; hp.x = bx; hp.y = by;
    hi = *(uint32_t*)&hp;
    lo = bf2(x - __bfloat162float(bx), y - __bfloat162float(by));
}

// Split fp32 pair -> bf16 hi/lo pairs into SW128 row: [hi 32 bf16 | lo 32 bf16]
__device__ __forceinline__ void split_store_pair(char* base, int row, int col2,
                                                 float x0, float x1) {
    __nv_bfloat16 h0 = __float2bfloat16(x0);
    __nv_bfloat16 h1 = __float2bfloat16(x1);
    __nv_bfloat16 l0 = __float2bfloat16(x0 - __bfloat162float(h0));
    __nv_bfloat16 l1 = __float2bfloat16(x1 - __bfloat162float(h1));
    __nv_bfloat162 hp; hp.x = h0; hp.y = h1;
    __nv_bfloat162 lp; lp.x = l0; lp.y = l1;
    *(__nv_bfloat162*)(base + sw128(row * 128 + col2 * 2)) = hp;
    *(__nv_bfloat162*)(base + sw128(row * 128 + 64 + col2 * 2)) = lp;
}

__constant__ int c_aofs[3] = {0, 0, 32};
__constant__ int c_bofs[3] = {0, 32, 0};

// ---------------------------------------------------------------------------
// tc_gemm: C[M,N] = A[M,K]*B[N,K]^T (bf16x3). Tile 128x128, BK=32, 8 warps.
// (unchanged from R4 — used for projections, rel, final)
// ---------------------------------------------------------------------------
__global__ __launch_bounds__(256) void tc_gemm(
    const float* __restrict__ Ag, const float* __restrict__ Bg,
    float* __restrict__ Cg, int K, int lda, int ldb, int ldc,
    const float* __restrict__ bias)
{
    __shared__ __align__(128) char smA[128 * 128];
    __shared__ __align__(128) char smB[128 * 128];

    const int tid = threadIdx.x;
    const int warp = tid >> 5, lane = tid & 31;
    const float* A = Ag;
    const float* B = Bg;
    float* C = Cg;
    const int row0 = blockIdx.y * 128;
    const int col0 = blockIdx.x * 128;
    const int wm0 = (warp >> 1) * 32;
    const int wn0 = (warp & 1) * 64;

    uint32_t sA = smem_u32(smA);
    uint32_t sB = smem_u32(smB);

    float c[2][8][4];
#pragma unroll
    for (int i = 0; i < 2; i++)
#pragma unroll
        for (int j = 0; j < 8; j++)
#pragma unroll
            for (int t = 0; t < 4; t++) c[i][j][t] = 0.f;

    const int lr = tid >> 4;
    const int lp = tid & 15;

    for (int k0 = 0; k0 < K; k0 += 32) {
#pragma unroll
        for (int s = 0; s < 8; s++) {
            int r = s * 16 + lr;
            float2 va = *(const float2*)&A[(size_t)(row0 + r) * lda + k0 + 2 * lp];
            split_store_pair(smA, r, 2 * lp, va.x, va.y);
            float2 vb = *(const float2*)&B[(size_t)(col0 + r) * ldb + k0 + 2 * lp];
            split_store_pair(smB, r, 2 * lp, vb.x, vb.y);
        }
        __syncthreads();

        const int arow = wm0 + (lane & 15);
        const int acolq = (lane >> 4) * 8;
        const int bn = wn0 + (lane & 7) + ((lane >> 4) << 3);
        const int bkq = ((lane >> 3) & 1) * 8;

#pragma unroll
        for (int s3 = 0; s3 < 3; s3++) {
            const int aoff = c_aofs[s3], boff = c_bofs[s3];
#pragma unroll
            for (int ks = 0; ks < 2; ks++) {
                int acol = aoff + ks * 16 + acolq;
                uint32_t a0[4], a1[4];
                ldsm4(a0, sA + sw128((uint32_t)(arow * 128 + acol * 2)));
                ldsm4(a1, sA + sw128((uint32_t)((arow + 16) * 128 + acol * 2)));
                int bcol = boff + ks * 16 + bkq;
                uint32_t bq[4][4];
#pragma unroll
                for (int j2 = 0; j2 < 4; j2++)
                    ldsm4(bq[j2], sB + sw128((uint32_t)((bn + j2 * 16) * 128 + bcol * 2)));
#pragma unroll
                for (int i = 0; i < 2; i++) {
                    const uint32_t* ai = (i == 0) ? a0 : a1;
#pragma unroll
                    for (int j = 0; j < 8; j++)
                        mma16816(c[i][j], ai, &bq[j >> 1][(j & 1) * 2]);
                }
            }
        }
        __syncthreads();
    }

    const int g = lane >> 2, t4 = lane & 3;
#pragma unroll
    for (int i = 0; i < 2; i++) {
#pragma unroll
        for (int j = 0; j < 8; j++) {
            int gr0 = row0 + wm0 + i * 16 + g;
            int gc = col0 + wn0 + j * 8 + t4 * 2;
            float v0 = c[i][j][0], v1 = c[i][j][1];
            float v2 = c[i][j][2], v3 = c[i][j][3];
            if (bias) {
                float2 bv = *(const float2*)&bias[gc];
                v0 += bv.x; v1 += bv.y; v2 += bv.x; v3 += bv.y;
            }
            *(float2*)&C[(size_t)gr0 * ldc + gc] = make_float2(v0, v1);
            *(float2*)&C[(size_t)(gr0 + 8) * ldc + gc] = make_float2(v2, v3);
        }
    }
}

// ---------------------------------------------------------------------------
// fused_attn: per (head, 128-row block):
//   pass1: online row max/sum of exp((q k^T + rel)*SCALE)
//   pass2: recompute scores, w = exp(s-m)/l -> gmem; PV accumulate via
//          C-frag -> A-frag reuse (bf16 hi/lo), attn -> g_attn
// smem (dynamic 64KB): khi/klo [128 t x 64 d bf16], vhi/vlo [2][64 d x 64 t]
// ---------------------------------------------------------------------------
__global__ __launch_bounds__(256) void fused_attn(
    const float* __restrict__ rel, float* __restrict__ wout)
{
    extern __shared__ char dyn[];
    char* skh = dyn;
    char* skl = dyn + 16384;
    char* svh = dyn + 32768;
    char* svl = dyn + 49152;

    const int tid = threadIdx.x;
    const int warp = tid >> 5, lane = tid & 31;
    const int g = lane >> 2, t4 = lane & 3;
    const int h = blockIdx.y;
    const int row0 = blockIdx.x * 128;
    const int qc0 = h * HD;

    const uint32_t uSkh = smem_u32(skh);
    const uint32_t uSkl = smem_u32(skl);
    const uint32_t uSvh = smem_u32(svh);
    const uint32_t uSvl = smem_u32(svl);

    const int rA = row0 + warp * 16 + g;    // this thread's row (low)
    const int rB = rA + 8;                  // high row

    // --- q fragments (resident): qh/ql[kstep][reg] ---
    uint32_t qh[4][4], ql[4][4];
#pragma unroll
    for (int ks = 0; ks < 4; ks++) {
        int c = qc0 + ks * 16 + 2 * t4;
        float2 x00 = *(const float2*)&g_q[(size_t)rA * E + c];
        float2 x10 = *(const float2*)&g_q[(size_t)rB * E + c];
        float2 x01 = *(const float2*)&g_q[(size_t)rA * E + c + 8];
        float2 x11 = *(const float2*)&g_q[(size_t)rB * E + c + 8];
        split2(x00.x, x00.y, qh[ks][0], ql[ks][0]);
        split2(x10.x, x10.y, qh[ks][1], ql[ks][1]);
        split2(x01.x, x01.y, qh[ks][2], ql[ks][2]);
        split2(x11.x, x11.y, qh[ks][3], ql[ks][3]);
    }

    const int lr = tid >> 4, lp = tid & 15;
    const int bnp = (lane & 7) + ((lane >> 4) << 3);  // ldmatrix row pattern
    const int bkq = ((lane >> 3) & 1) * 8;            // ldmatrix col pattern

    float mA = -1e30f, mB = -1e30f, lA = 0.f, lB = 0.f;

    // ===================== PASS 1 =====================
#pragma unroll 1
    for (int t0 = 0; t0 < S; t0 += 128) {
        __syncthreads();
#pragma unroll
        for (int s = 0; s < 8; s++) {
            int tr = s * 16 + lr;
            float4 kv = *(const float4*)&g_k[(size_t)(t0 + tr) * E + qc0 + 4 * lp];
            uint32_t h0, l0, h1, l1;
            split2(kv.x, kv.y, h0, l0);
            split2(kv.z, kv.w, h1, l1);
            *(uint2*)(skh + sw128(tr * 128 + 8 * lp)) = make_uint2(h0, h1);
            *(uint2*)(skl + sw128(tr * 128 + 8 * lp)) = make_uint2(l0, l1);
        }
        __syncthreads();

#pragma unroll 1
        for (int ch = 0; ch < 8; ch++) {
            float cs[2][4];
#pragma unroll
            for (int i = 0; i < 2; i++)
#pragma unroll
                for (int t = 0; t < 4; t++) cs[i][t] = 0.f;
            int brow = ch * 16 + bnp;
#pragma unroll
            for (int ks = 0; ks < 4; ks++) {
                uint32_t bh[4], bl[4];
                uint32_t cb = (uint32_t)((ks * 16 + bkq) * 2);
                ldsm4(bh, uSkh + sw128(brow * 128 + cb));
                ldsm4(bl, uSkl + sw128(brow * 128 + cb));
                mma16816(cs[0], qh[ks], bh + 0);
                mma16816(cs[1], qh[ks], bh + 2);
                mma16816(cs[0], qh[ks], bl + 0);
                mma16816(cs[1], qh[ks], bl + 2);
                mma16816(cs[0], ql[ks], bh + 0);
                mma16816(cs[1], ql[ks], bh + 2);
            }
            int cg = t0 + ch * 16 + 2 * t4;
            float2 r00 = *(const float2*)&rel[(size_t)rA * S + cg];
            float2 r10 = *(const float2*)&rel[(size_t)rB * S + cg];
            float2 r01 = *(const float2*)&rel[(size_t)rA * S + cg + 8];
            float2 r11 = *(const float2*)&rel[(size_t)rB * S + cg + 8];
            float sA0 = (cs[0][0] + r00.x) * SCALE, sA1 = (cs[0][1] + r00.y) * SCALE;
            float sA2 = (cs[1][0] + r01.x) * SCALE, sA3 = (cs[1][1] + r01.y) * SCALE;
            float sB0 = (cs[0][2] + r10.x) * SCALE, sB1 = (cs[0][3] + r10.y) * SCALE;
            float sB2 = (cs[1][2] + r11.x) * SCALE, sB3 = (cs[1][3] + r11.y) * SCALE;

            float mxA = fmaxf(fmaxf(sA0, sA1), fmaxf(sA2, sA3));
            float mxB = fmaxf(fmaxf(sB0, sB1), fmaxf(sB2, sB3));
            mxA = fmaxf(mxA, __shfl_xor_sync(0xffffffffu, mxA, 1));
            mxA = fmaxf(mxA, __shfl_xor_sync(0xffffffffu, mxA, 2));
            mxB = fmaxf(mxB, __shfl_xor_sync(0xffffffffu, mxB, 1));
            mxB = fmaxf(mxB, __shfl_xor_sync(0xffffffffu, mxB, 2));
            float nmA = fmaxf(mA, mxA), nmB = fmaxf(mB, mxB);
            float suA = __expf(sA0 - nmA) + __expf(sA1 - nmA) +
                        __expf(sA2 - nmA) + __expf(sA3 - nmA);
            float suB = __expf(sB0 - nmB) + __expf(sB1 - nmB) +
                        __expf(sB2 - nmB) + __expf(sB3 - nmB);
            suA += __shfl_xor_sync(0xffffffffu, suA, 1);
            suA += __shfl_xor_sync(0xffffffffu, suA, 2);
            suB += __shfl_xor_sync(0xffffffffu, suB, 1);
            suB += __shfl_xor_sync(0xffffffffu, suB, 2);
            lA = lA * __expf(mA - nmA) + suA;
            lB = lB * __expf(mB - nmB) + suB;
            mA = nmA; mB = nmB;
        }
    }

    const float invA = 1.f / lA, invB = 1.f / lB;

    // PV accumulators: 8 n8 d-tiles x 4
    float o[8][4];
#pragma unroll
    for (int j = 0; j < 8; j++)
#pragma unroll
        for (int t = 0; t < 4; t++) o[j][t] = 0.f;

    float* wrow = wout + (size_t)h * S * S;

    // ===================== PASS 2 =====================
#pragma unroll 1
    for (int t0 = 0; t0 < S; t0 += 128) {
        __syncthreads();
#pragma unroll
        for (int s = 0; s < 8; s++) {
            int tr = s * 16 + lr;
            float4 kv = *(const float4*)&g_k[(size_t)(t0 + tr) * E + qc0 + 4 * lp];
            uint32_t h0, l0, h1, l1;
            split2(kv.x, kv.y, h0, l0);
            split2(kv.z, kv.w, h1, l1);
            *(uint2*)(skh + sw128(tr * 128 + 8 * lp)) = make_uint2(h0, h1);
            *(uint2*)(skl + sw128(tr * 128 + 8 * lp)) = make_uint2(l0, l1);

            float4 vv = *(const float4*)&g_v[(size_t)(t0 + tr) * E + qc0 + 4 * lp];
            int sub = tr >> 6, tc = tr & 63;
            char* bh_ = svh + sub * 8192;
            char* bl_ = svl + sub * 8192;
            float vs[4] = {vv.x, vv.y, vv.z, vv.w};
#pragma unroll
            for (int j = 0; j < 4; j++) {
                int d = 4 * lp + j;
                __nv_bfloat16 hb = __float2bfloat16(vs[j]);
                __nv_bfloat16 lb = __float2bfloat16(vs[j] - __bfloat162float(hb));
                *(__nv_bfloat16*)(bh_ + sw128(d * 128 + tc * 2)) = hb;
                *(__nv_bfloat16*)(bl_ + sw128(d * 128 + tc * 2)) = lb;
            }
        }
        __syncthreads();

#pragma unroll 1
        for (int ch = 0; ch < 8; ch++) {
            float cs[2][4];
#pragma unroll
            for (int i = 0; i < 2; i++)
#pragma unroll
                for (int t = 0; t < 4; t++) cs[i][t] = 0.f;
            int brow = ch * 16 + bnp;
#pragma unroll
            for (int ks = 0; ks < 4; ks++) {
                uint32_t bh[4], bl[4];
                uint32_t cb = (uint32_t)((ks * 16 + bkq) * 2);
                ldsm4(bh, uSkh + sw128(brow * 128 + cb));
                ldsm4(bl, uSkl + sw128(brow * 128 + cb));
                mma16816(cs[0], qh[ks], bh + 0);
                mma16816(cs[1], qh[ks], bh + 2);
                mma16816(cs[0], qh[ks], bl + 0);
                mma16816(cs[1], qh[ks], bl + 2);
                mma16816(cs[0], ql[ks], bh + 0);
                mma16816(cs[1], ql[ks], bh + 2);
            }
            int cg = t0 + ch * 16 + 2 * t4;
            float2 r00 = *(const float2*)&rel[(size_t)rA * S + cg];
            float2 r10 = *(const float2*)&rel[(size_t)rB * S + cg];
            float2 r01 = *(const float2*)&rel[(size_t)rA * S + cg + 8];
            float2 r11 = *(const float2*)&rel[(size_t)rB * S + cg + 8];
            float wA0 = __expf((cs[0][0] + r00.x) * SCALE - mA) * invA;
            float wA1 = __expf((cs[0][1] + r00.y) * SCALE - mA) * invA;
            float wA2 = __expf((cs[1][0] + r01.x) * SCALE - mA) * invA;
            float wA3 = __expf((cs[1][1] + r01.y) * SCALE - mA) * invA;
            float wB0 = __expf((cs[0][2] + r10.x) * SCALE - mB) * invB;
            float wB1 = __expf((cs[0][3] + r10.y) * SCALE - mB) * invB;
            float wB2 = __expf((cs[1][0 + 2] + r11.x) * SCALE - mB) * invB;
            float wB3 = __expf((cs[1][1 + 2] + r11.y) * SCALE - mB) * invB;
            // fix: cs[1][2], cs[1][3] are rB cols cg+8
            // (indices above already express that)

            // write w
            *(float2*)&wrow[(size_t)rA * S + cg]     = make_float2(wA0, wA1);
            *(float2*)&wrow[(size_t)rA * S + cg + 8] = make_float2(wA2, wA3);
            *(float2*)&wrow[(size_t)rB * S + cg]     = make_float2(wB0, wB1);
            *(float2*)&wrow[(size_t)rB * S + cg + 8] = make_float2(wB2, wB3);

            // pack w as A-frag (hi/lo)
            uint32_t ah[4], al[4];
            split2(wA0, wA1, ah[0], al[0]);
            split2(wB0, wB1, ah[1], al[1]);
            split2(wA2, wA3, ah[2], al[2]);
            split2(wB2, wB3, ah[3], al[3]);

            // PV MMAs against v tiles
            int sub = ch >> 2;
            uint32_t cb = (uint32_t)(((ch & 3) * 16 + bkq) * 2);
            uint32_t vbaseh = uSvh + sub * 8192;
            uint32_t vbasel = uSvl + sub * 8192;
#pragma unroll
            for (int jd = 0; jd < 4; jd++) {
                int dn = jd * 16 + bnp;
                uint32_t vh[4], vl[4];
                ldsm4(vh, vbaseh + sw128(dn * 128 + cb));
                ldsm4(vl, vbasel + sw128(dn * 128 + cb));
                mma16816(o[2 * jd],     ah, vh + 0);
                mma16816(o[2 * jd + 1], ah, vh + 2);
                mma16816(o[2 * jd],     ah, vl + 0);
                mma16816(o[2 * jd + 1], ah, vl + 2);
                mma16816(o[2 * jd],     al, vh + 0);
                mma16816(o[2 * jd + 1], al, vh + 2);
            }
        }
    }

    // epilogue: attn -> g_attn
#pragma unroll
    for (int j = 0; j < 8; j++) {
        int gc = qc0 + j * 8 + 2 * t4;
        *(float2*)&g_attn[(size_t)rA * E + gc] = make_float2(o[j][0], o[j][1]);
        *(float2*)&g_attn[(size_t)rB * E + gc] = make_float2(o[j][2], o[j][3]);
    }
}

// ---------------------------------------------------------------------------
// Launch
// ---------------------------------------------------------------------------
extern "C" void kernel_launch(void* const* d_in, const int* in_sizes, int n_in,
                              void* d_out, int out_size)
{
    (void)in_sizes; (void)n_in; (void)out_size;
    const float* query = (const float*)d_in[0];
    const float* key   = (const float*)d_in[1];
    const float* value = (const float*)d_in[2];
    const float* sim   = (const float*)d_in[3];
    const float* Wq    = (const float*)d_in[4];
    const float* bq    = (const float*)d_in[5];
    const float* Wk    = (const float*)d_in[6];
    const float* bk    = (const float*)d_in[7];
    const float* Wv    = (const float*)d_in[8];
    const float* bv    = (const float*)d_in[9];
    const float* Wo    = (const float*)d_in[10];
    const float* bo    = (const float*)d_in[11];

    float* out = (float*)d_out;                 // [S,E]
    float* w   = out + (size_t)S * E;           // [H,S,S]

    float *gq, *gk, *gv, *grel, *gattn;
    cudaGetSymbolAddress((void**)&gq,    g_q);
    cudaGetSymbolAddress((void**)&gk,    g_k);
    cudaGetSymbolAddress((void**)&gv,    g_v);
    cudaGetSymbolAddress((void**)&grel,  g_rel);
    cudaGetSymbolAddress((void**)&gattn, g_attn);

    static int attr_done = 0;
    if (!attr_done) {
        cudaFuncSetAttribute(fused_attn,
                             cudaFuncAttributeMaxDynamicSharedMemorySize, 65536);
        attr_done = 1;
    }

    dim3 blk(256);

    // Projections
    tc_gemm<<<dim3(E / 128, S / 128), blk>>>(query, Wq, gq, E, E, E, E, bq);
    tc_gemm<<<dim3(E / 128, S / 128), blk>>>(key,   Wk, gk, E, E, E, E, bk);
    tc_gemm<<<dim3(E / 128, S / 128), blk>>>(value, Wv, gv, E, E, E, E, bv);

    // rel = sim @ sim^T
    tc_gemm<<<dim3(S / 128, S / 128), blk>>>(sim, sim, grel, 64, 64, 64, S, nullptr);

    // fused attention: scores + softmax + w write + PV
    fused_attn<<<dim3(S / 128, H), blk, 65536>>>(grel, w);

    // out = attn @ Wo^T + bo
    tc_gemm<<<dim3(E / 128, S / 128), blk>>>(gattn, Wo, out, E, E, E, E, bo);
}